// round 5
// baseline (speedup 1.0000x reference)
#include <cuda_runtime.h>
#include <cuda_bf16.h>

// Problem constants (B=1, L=1024, TOKEN_Z=128, R_MAX=32, S_MAX=2)
#define LSEQ   1024
#define JHALF  512          // each block handles half a row
#define TZ4    32           // 128 channels as float4
// W rows: [0,66)=W_pos, [66,132)=W_tok, 132=w_ent, [133,139)=W_ch
//
// Folded table T (70 rows of 32 float4 = 35840 B):
//   T[0..64]  = D[dr] = W_pos[dr] + W_tok[65] + W_ch[5]   (same-chain, dt=65)
//   T[65..69] = C[dc] = W_pos[65] + W_tok[65] + W_ch[dc]  (diff-chain)
// Rare same-residue fixup (+W_tok[dt]-W_tok[65]) reads W from global (L2-hot).
#define NT 70
// smem: 70*32*16 + 512*4 = 35840 + 2048 = 37888 bytes -> 5 CTAs/SM (189 KB)
#define SMEM_BYTES (NT * TZ4 * 16 + JHALF * 4)

__device__ __forceinline__ float4 f4add(float4 a, float4 b) {
    return make_float4(a.x + b.x, a.y + b.y, a.z + b.z, a.w + b.w);
}

__global__ __launch_bounds__(256, 5)
void relpos_kernel(const int* __restrict__ asym,
                   const int* __restrict__ resi,
                   const int* __restrict__ ent,
                   const int* __restrict__ tok,
                   const int* __restrict__ sym,
                   const int* __restrict__ cyc,
                   const float* __restrict__ W,
                   float* __restrict__ out)
{
    extern __shared__ char smem_raw[];
    float4* sT    = reinterpret_cast<float4*>(smem_raw);
    int*    sDesc = reinterpret_cast<int*>(sT + NT * TZ4);

    const int tid  = threadIdx.x;
    const int lane = tid & 31;
    const int i     = blockIdx.x >> 1;          // row
    const int jbase = (blockIdx.x & 1) * JHALF; // half-row offset

    const float4* W4 = reinterpret_cast<const float4*>(W);

    // ---- Build folded table: each thread owns a fixed lane, strides rows ----
    {
        const float4 wtok65 = __ldg(&W4[(66 + 65) * TZ4 + lane]);
        const float4 wch5   = __ldg(&W4[(133 + 5) * TZ4 + lane]);
        const float4 base65 = f4add(__ldg(&W4[65 * TZ4 + lane]), wtok65); // Wpos65+Wtok65
        const int row0 = tid >> 5;   // 0..7
        #pragma unroll
        for (int r = row0; r < NT; r += 8) {
            float4 v;
            if (r < 65) {
                v = f4add(f4add(__ldg(&W4[r * TZ4 + lane]), wtok65), wch5);
            } else {
                v = f4add(base65, __ldg(&W4[(133 + (r - 65)) * TZ4 + lane]));
            }
            sT[r * TZ4 + lane] = v;
        }
    }

    // ---- Per-block scalars ----
    const int ai = __ldg(&asym[i]);
    const int ri = __ldg(&resi[i]);
    const int ei = __ldg(&ent[i]);
    const int ti = __ldg(&tok[i]);
    const int si = __ldg(&sym[i]);

    // ---- Descriptors: idxT | idxB<<8 (0xFF = none) | e<<16 ----
    #pragma unroll 2
    for (int jj = tid; jj < JHALF; jj += 256) {
        const int j = jbase + jj;
        const int aj = __ldg(&asym[j]);
        int idxT, idxB = 0xFF;
        if (ai == aj) {
            const int rj = __ldg(&resi[j]);
            int rel = ri - rj;
            const int cj = __ldg(&cyc[j]);
            const int period = (cj > 0) ? cj : 10000;
            const float q = rintf((float)rel / (float)period);
            rel -= (int)((float)period * q);
            idxT = min(max(rel + 32, 0), 64);                 // d_residue -> D row
            if (ri == rj)                                     // rare: needs W_tok fixup
                idxB = min(max(ti - __ldg(&tok[j]) + 32, 0), 64);
        } else {
            idxT = 65 + min(max(si - __ldg(&sym[j]) + 2, 0), 4); // C row
        }
        const int e = (ei == __ldg(&ent[j])) ? 1 : 0;
        sDesc[jj] = idxT | (idxB << 8) | (e << 16);
    }
    __syncthreads();

    // ---- Register-resident w_ent slice for this lane ----
    const float4 went = __ldg(&W4[132 * TZ4 + lane]);

    const int warp = tid >> 5;
    float4* out4 = reinterpret_cast<float4*>(out)
                 + (size_t)i * LSEQ * TZ4 + (size_t)jbase * TZ4;
    const int2* sDesc2 = reinterpret_cast<const int2*>(sDesc);

    // Warp handles 2 consecutive j per iteration -> 1KB contiguous store span.
    #pragma unroll 4
    for (int k = 0; k < 32; k++) {
        const int u  = warp + k * 8;       // int2 index: j0 = 2*u
        const int2 d = sDesc2[u];          // broadcast LDS.64 (2 descriptors)

        float4 r0 = sT[(d.x & 0xFF) * TZ4 + lane];
        float4 r1 = sT[(d.y & 0xFF) * TZ4 + lane];

        if (d.x & 0x10000) r0 = f4add(r0, went);
        if (d.y & 0x10000) r1 = f4add(r1, went);

        // Rare same-residue fixup: + W_tok[dt] - W_tok[65]  (warp-uniform, L2-hot)
        const int b0 = (d.x >> 8) & 0xFF;
        const int b1 = (d.y >> 8) & 0xFF;
        if (b0 != 0xFF) {
            const float4 wt = __ldg(&W4[(66 + b0) * TZ4 + lane]);
            const float4 w65 = __ldg(&W4[(66 + 65) * TZ4 + lane]);
            r0 = make_float4(r0.x + wt.x - w65.x, r0.y + wt.y - w65.y,
                             r0.z + wt.z - w65.z, r0.w + wt.w - w65.w);
        }
        if (b1 != 0xFF) {
            const float4 wt = __ldg(&W4[(66 + b1) * TZ4 + lane]);
            const float4 w65 = __ldg(&W4[(66 + 65) * TZ4 + lane]);
            r1 = make_float4(r1.x + wt.x - w65.x, r1.y + wt.y - w65.y,
                             r1.z + wt.z - w65.z, r1.w + wt.w - w65.w);
        }

        float4* p = out4 + (size_t)(2 * u) * TZ4 + lane;
        __stcs(p,       r0);
        __stcs(p + TZ4, r1);
    }
}

extern "C" void kernel_launch(void* const* d_in, const int* in_sizes, int n_in,
                              void* d_out, int out_size) {
    const int*   asym = (const int*)d_in[0];
    const int*   resi = (const int*)d_in[1];
    const int*   entp = (const int*)d_in[2];
    const int*   tokp = (const int*)d_in[3];
    const int*   symp = (const int*)d_in[4];
    const int*   cycp = (const int*)d_in[5];
    const float* W    = (const float*)d_in[6];
    float* out = (float*)d_out;

    cudaFuncSetAttribute(relpos_kernel,
                         cudaFuncAttributeMaxDynamicSharedMemorySize, SMEM_BYTES);

    relpos_kernel<<<2 * LSEQ, 256, SMEM_BYTES>>>(asym, resi, entp, tokp, symp, cycp, W, out);
}

// round 6
// speedup vs baseline: 1.0256x; 1.0256x over previous
#include <cuda_runtime.h>
#include <cuda_bf16.h>

// Problem constants (B=1, L=1024, TOKEN_Z=128, R_MAX=32, S_MAX=2)
#define LSEQ   1024
#define JQ     256          // each block handles a quarter row
#define TZ4    32           // 128 channels as float4
// W rows: [0,66)=W_pos, [66,132)=W_tok, 132=w_ent, [133,139)=W_ch
//
// Folded table T (70 rows of 32 float4 = 35840 B):
//   T[0..64]  = D[dr] = W_pos[dr] + W_tok[65] + W_ch[5]   (same-chain, dt=65)
//   T[65..69] = C[dc] = W_pos[65] + W_tok[65] + W_ch[dc]  (diff-chain)
// Rare same-residue fixup (+W_tok[dt]-W_tok[65]) reads W from global (L2-hot).
#define NT 70
// smem: 70*32*16 + 256*4 = 35840 + 1024 = 36864 bytes -> 5 CTAs/SM
#define SMEM_BYTES (NT * TZ4 * 16 + JQ * 4)

__device__ __forceinline__ float4 f4add(float4 a, float4 b) {
    return make_float4(a.x + b.x, a.y + b.y, a.z + b.z, a.w + b.w);
}

__global__ __launch_bounds__(256, 5)
void relpos_kernel(const int* __restrict__ asym,
                   const int* __restrict__ resi,
                   const int* __restrict__ ent,
                   const int* __restrict__ tok,
                   const int* __restrict__ sym,
                   const int* __restrict__ cyc,
                   const float* __restrict__ W,
                   float* __restrict__ out)
{
    extern __shared__ char smem_raw[];
    float4* sT    = reinterpret_cast<float4*>(smem_raw);
    int*    sDesc = reinterpret_cast<int*>(sT + NT * TZ4);

    const int tid  = threadIdx.x;
    const int lane = tid & 31;
    const int i     = blockIdx.x >> 2;         // row
    const int jbase = (blockIdx.x & 3) * JQ;   // quarter-row offset

    const float4* W4 = reinterpret_cast<const float4*>(W);

    // ---- Build folded table: each thread owns a fixed lane, strides rows ----
    {
        const float4 wtok65 = __ldg(&W4[(66 + 65) * TZ4 + lane]);
        const float4 wch5   = __ldg(&W4[(133 + 5) * TZ4 + lane]);
        const float4 base65 = f4add(__ldg(&W4[65 * TZ4 + lane]), wtok65); // Wpos65+Wtok65
        const int row0 = tid >> 5;   // 0..7
        #pragma unroll
        for (int r = row0; r < NT; r += 8) {
            float4 v;
            if (r < 65) {
                v = f4add(f4add(__ldg(&W4[r * TZ4 + lane]), wtok65), wch5);
            } else {
                v = f4add(base65, __ldg(&W4[(133 + (r - 65)) * TZ4 + lane]));
            }
            sT[r * TZ4 + lane] = v;
        }
    }

    // ---- Per-block scalars ----
    const int ai = __ldg(&asym[i]);
    const int ri = __ldg(&resi[i]);
    const int ei = __ldg(&ent[i]);
    const int ti = __ldg(&tok[i]);
    const int si = __ldg(&sym[i]);

    // ---- Descriptor: exactly one per thread. idxT | idxB<<8 (0xFF=none) | e<<16 ----
    {
        const int j = jbase + tid;
        const int aj = __ldg(&asym[j]);
        int idxT, idxB = 0xFF;
        if (ai == aj) {
            const int rj = __ldg(&resi[j]);
            int rel = ri - rj;
            const int cj = __ldg(&cyc[j]);
            const int period = (cj > 0) ? cj : 10000;
            const float q = rintf((float)rel / (float)period);
            rel -= (int)((float)period * q);
            idxT = min(max(rel + 32, 0), 64);                 // d_residue -> D row
            if (ri == rj)                                     // rare: needs W_tok fixup
                idxB = min(max(ti - __ldg(&tok[j]) + 32, 0), 64);
        } else {
            idxT = 65 + min(max(si - __ldg(&sym[j]) + 2, 0), 4); // C row
        }
        const int e = (ei == __ldg(&ent[j])) ? 1 : 0;
        sDesc[tid] = idxT | (idxB << 8) | (e << 16);
    }
    __syncthreads();

    // ---- Register-resident w_ent slice for this lane ----
    const float4 went = __ldg(&W4[132 * TZ4 + lane]);

    const int warp = tid >> 5;
    float4* out4 = reinterpret_cast<float4*>(out)
                 + (size_t)i * LSEQ * TZ4 + (size_t)jbase * TZ4;
    const int2* sDesc2 = reinterpret_cast<const int2*>(sDesc);

    // Warp handles 2 consecutive j per iteration -> 1KB contiguous store span.
    #pragma unroll 4
    for (int k = 0; k < 16; k++) {
        const int u  = warp + k * 8;       // int2 index: j0 = 2*u
        const int2 d = sDesc2[u];          // broadcast LDS.64 (2 descriptors)

        float4 r0 = sT[(d.x & 0xFF) * TZ4 + lane];
        float4 r1 = sT[(d.y & 0xFF) * TZ4 + lane];

        if (d.x & 0x10000) r0 = f4add(r0, went);
        if (d.y & 0x10000) r1 = f4add(r1, went);

        // Rare same-residue fixup: + W_tok[dt] - W_tok[65]  (warp-uniform, L2-hot)
        const int b0 = (d.x >> 8) & 0xFF;
        const int b1 = (d.y >> 8) & 0xFF;
        if (b0 != 0xFF) {
            const float4 wt  = __ldg(&W4[(66 + b0) * TZ4 + lane]);
            const float4 w65 = __ldg(&W4[(66 + 65) * TZ4 + lane]);
            r0 = make_float4(r0.x + wt.x - w65.x, r0.y + wt.y - w65.y,
                             r0.z + wt.z - w65.z, r0.w + wt.w - w65.w);
        }
        if (b1 != 0xFF) {
            const float4 wt  = __ldg(&W4[(66 + b1) * TZ4 + lane]);
            const float4 w65 = __ldg(&W4[(66 + 65) * TZ4 + lane]);
            r1 = make_float4(r1.x + wt.x - w65.x, r1.y + wt.y - w65.y,
                             r1.z + wt.z - w65.z, r1.w + wt.w - w65.w);
        }

        float4* p = out4 + (size_t)(2 * u) * TZ4 + lane;
        __stcs(p,       r0);
        __stcs(p + TZ4, r1);
    }
}

extern "C" void kernel_launch(void* const* d_in, const int* in_sizes, int n_in,
                              void* d_out, int out_size) {
    const int*   asym = (const int*)d_in[0];
    const int*   resi = (const int*)d_in[1];
    const int*   entp = (const int*)d_in[2];
    const int*   tokp = (const int*)d_in[3];
    const int*   symp = (const int*)d_in[4];
    const int*   cycp = (const int*)d_in[5];
    const float* W    = (const float*)d_in[6];
    float* out = (float*)d_out;

    cudaFuncSetAttribute(relpos_kernel,
                         cudaFuncAttributeMaxDynamicSharedMemorySize, SMEM_BYTES);

    relpos_kernel<<<4 * LSEQ, 256, SMEM_BYTES>>>(asym, resi, entp, tokp, symp, cycp, W, out);
}